// round 2
// baseline (speedup 1.0000x reference)
#include <cuda_runtime.h>
#include <math.h>

#define T_STEPS 256
#define B_SZ    64
#define D_SZ    1024
#define H_SZ    1024
#define NG      4096   // 4*H
#define KDH     2048   // D+H

// Device-global scratch (allocation-free contract)
__device__ float g_Wxp[(size_t)D_SZ * NG];                 // [k][j]   16 MB
__device__ float g_Whp[(size_t)H_SZ * NG];                 // [k][j]   16 MB
__device__ float g_bias[NG];
__device__ float g_Xpre[(size_t)T_STEPS * B_SZ * NG];      // 268 MB
__device__ float g_hbuf[2][B_SZ * H_SZ];
__device__ float g_c[B_SZ * H_SZ];

// ---------------------------------------------------------------------------
// Repack weights: gate-fused [K][4H] layouts for x-part and h-part + bias.
// ---------------------------------------------------------------------------
__global__ void pack_weights(const float* __restrict__ Wf, const float* __restrict__ bf,
                             const float* __restrict__ Wi, const float* __restrict__ bi,
                             const float* __restrict__ Wg, const float* __restrict__ bg,
                             const float* __restrict__ Wo, const float* __restrict__ bo) {
    int idx = blockIdx.x * blockDim.x + threadIdx.x;
    if (idx >= D_SZ * NG) return;
    int k  = idx >> 12;          // / 4096
    int j  = idx & (NG - 1);
    int g  = j >> 10;
    int jj = j & 1023;
    const float* W = (g == 0) ? Wf : (g == 1) ? Wi : (g == 2) ? Wg : Wo;
    g_Wxp[(size_t)k * NG + j] = W[(size_t)jj * KDH + k];
    g_Whp[(size_t)k * NG + j] = W[(size_t)jj * KDH + D_SZ + k];
    if (k == 0) {
        const float* bb = (g == 0) ? bf : (g == 1) ? bi : (g == 2) ? bg : bo;
        g_bias[j] = bb[jj];
    }
}

__global__ void zero_state() {
    int i = blockIdx.x * blockDim.x + threadIdx.x;
    if (i < B_SZ * H_SZ) {
        g_hbuf[0][i] = 0.f;
        g_hbuf[1][i] = 0.f;
        g_c[i]       = 0.f;
    }
}

// ---------------------------------------------------------------------------
// Precompute GEMM: Xpre[M=T*B, 4H] = inputs[M, D] @ Wxp[D, 4H] + bias
// 64x64 tile, BK=16, 256 threads, 4x4 register tile.
// ---------------------------------------------------------------------------
__global__ void gemm_xpre(const float* __restrict__ A) {
    __shared__ float As[16][68];   // padded: store-transpose, float4-aligned rows
    __shared__ float Bs[16][64];
    const int bx  = blockIdx.x;    // N tile (0..63)
    const int by  = blockIdx.y;    // M tile (0..255)
    const int tid = threadIdx.x;
    const int tx  = tid & 15;
    const int ty  = tid >> 4;
    float acc[4][4] = {};
    const float* Ab = A + (size_t)by * 64 * D_SZ;
    const size_t bcol = (size_t)bx * 64;

    for (int k0 = 0; k0 < D_SZ; k0 += 16) {
#pragma unroll
        for (int i = 0; i < 4; i++) {
            int e = tid + i * 256;
            int r = e >> 4, c = e & 15;
            As[c][r] = Ab[(size_t)r * D_SZ + k0 + c];
            int r2 = e >> 6, c2 = e & 63;
            Bs[r2][c2] = g_Wxp[(size_t)(k0 + r2) * NG + bcol + c2];
        }
        __syncthreads();
#pragma unroll
        for (int kk = 0; kk < 16; kk++) {
            float4 a4 = *reinterpret_cast<const float4*>(&As[kk][ty * 4]);
            float4 b4 = *reinterpret_cast<const float4*>(&Bs[kk][tx * 4]);
            float a[4] = {a4.x, a4.y, a4.z, a4.w};
            float b[4] = {b4.x, b4.y, b4.z, b4.w};
#pragma unroll
            for (int i = 0; i < 4; i++)
#pragma unroll
                for (int j = 0; j < 4; j++)
                    acc[i][j] += a[i] * b[j];
        }
        __syncthreads();
    }
#pragma unroll
    for (int i = 0; i < 4; i++) {
        size_t r = (size_t)by * 64 + ty * 4 + i;
#pragma unroll
        for (int j = 0; j < 4; j++) {
            size_t cidx = bcol + tx * 4 + j;
            g_Xpre[r * NG + cidx] = acc[i][j] + g_bias[cidx];
        }
    }
}

// ---------------------------------------------------------------------------
// One LSTM step: z = Xpre[t] + h_{t-1} @ Whp ; gate math ; c/h update.
// Grid: 128 blocks (8 jj-cols each), 128 threads.
// Thread tile: 4 batch rows x 1 jj x 4 gates (all four gates in-register so
// the epilogue does the nonlinearity without another kernel).
// ---------------------------------------------------------------------------
__global__ void lstm_step(int t, float* __restrict__ out) {
    __shared__ float Hs[16][68];
    __shared__ float Ws[16][32];
    const float* __restrict__ xpre_t = g_Xpre + (size_t)t * B_SZ * NG;
    const float* __restrict__ h_in   = g_hbuf[t & 1];
    float* __restrict__ h_out        = g_hbuf[(t + 1) & 1];
    float* __restrict__ out_t        = out + (size_t)t * B_SZ * H_SZ;

    const int jb  = blockIdx.x * 8;       // jj base
    const int tid = threadIdx.x;          // 128
    const int tx  = tid & 7;              // jj lane
    const int ty  = tid >> 3;             // 0..15 (row group)
    float acc[4][4] = {};                 // [batch row][gate]

    for (int k0 = 0; k0 < H_SZ; k0 += 16) {
#pragma unroll
        for (int i = 0; i < 8; i++) {
            int e = tid + i * 128;
            int r = e >> 4, c = e & 15;
            Hs[c][r] = h_in[r * H_SZ + k0 + c];
        }
#pragma unroll
        for (int i = 0; i < 4; i++) {
            int e = tid + i * 128;
            int r = e >> 5, c = e & 31;    // c = g*8 + jl
            int g = c >> 3, jl = c & 7;
            Ws[r][c] = g_Whp[(size_t)(k0 + r) * NG + (g << 10) + jb + jl];
        }
        __syncthreads();
#pragma unroll
        for (int kk = 0; kk < 16; kk++) {
            float4 h4v = *reinterpret_cast<const float4*>(&Hs[kk][ty * 4]);
            float h4[4] = {h4v.x, h4v.y, h4v.z, h4v.w};
            float w4[4];
#pragma unroll
            for (int g = 0; g < 4; g++) w4[g] = Ws[kk][(g << 3) + tx];
#pragma unroll
            for (int i = 0; i < 4; i++)
#pragma unroll
                for (int g = 0; g < 4; g++)
                    acc[i][g] += h4[i] * w4[g];
        }
        __syncthreads();
    }

    const int jj = jb + tx;
#pragma unroll
    for (int i = 0; i < 4; i++) {
        int b = ty * 4 + i;
        float zf = acc[i][0] + xpre_t[(size_t)b * NG + jj];
        float zi = acc[i][1] + xpre_t[(size_t)b * NG + 1024 + jj];
        float zg = acc[i][2] + xpre_t[(size_t)b * NG + 2048 + jj];
        float zo = acc[i][3] + xpre_t[(size_t)b * NG + 3072 + jj];
        float f  = 1.f / (1.f + expf(-zf));
        float ig = 1.f / (1.f + expf(-zi));
        float gg = tanhf(zg);
        float oo = 1.f / (1.f + expf(-zo));
        int idx  = b * H_SZ + jj;
        float cn = f * g_c[idx] + ig * gg;
        g_c[idx] = cn;
        float hn = oo * tanhf(cn);
        h_out[idx] = hn;
        out_t[idx] = hn;
    }
}

__global__ void write_tail(float* __restrict__ out_tail) {
    int i = blockIdx.x * blockDim.x + threadIdx.x;
    if (i < B_SZ * H_SZ) {
        out_tail[i] = g_hbuf[0][i];                // hx (final h; 256 steps -> buf 0)
        out_tail[B_SZ * H_SZ + i] = g_c[i];        // cx
    }
}

extern "C" void kernel_launch(void* const* d_in, const int* in_sizes, int n_in,
                              void* d_out, int out_size) {
    const float* inputs = (const float*)d_in[0];
    const float* Wf = (const float*)d_in[1];
    const float* bf = (const float*)d_in[2];
    const float* Wi = (const float*)d_in[3];
    const float* bi = (const float*)d_in[4];
    const float* Wg = (const float*)d_in[5];
    const float* bg = (const float*)d_in[6];
    const float* Wo = (const float*)d_in[7];
    const float* bo = (const float*)d_in[8];
    float* out = (float*)d_out;

    pack_weights<<<(D_SZ * NG + 255) / 256, 256>>>(Wf, bf, Wi, bi, Wg, bg, Wo, bo);
    zero_state<<<(B_SZ * H_SZ + 255) / 256, 256>>>();

    dim3 g1(NG / 64, (T_STEPS * B_SZ) / 64);
    gemm_xpre<<<g1, 256>>>(inputs);

    for (int t = 0; t < T_STEPS; t++) {
        lstm_step<<<128, 128>>>(t, out);
    }

    const int tail_needed = T_STEPS * B_SZ * H_SZ + 2 * B_SZ * H_SZ;
    if (out_size >= tail_needed) {
        write_tail<<<(B_SZ * H_SZ + 255) / 256, 256>>>(out + (size_t)T_STEPS * B_SZ * H_SZ);
    }
}

// round 3
// speedup vs baseline: 2.1704x; 2.1704x over previous
#include <cuda_runtime.h>
#include <cuda_fp16.h>
#include <math.h>

#define T_STEPS 256
#define B_SZ    64
#define H_SZ    1024
#define NG      4096   // 4*H

// ---------------- device-global scratch (allocation-free contract) ---------
__device__ __half g_Wxpk[(size_t)2 * NG * 1024];            // [s][n'=j*4+g][k]  16.8MB
__device__ __half g_Whpk[(size_t)128 * 2 * 32 * 1024];      // [blk][s][n32][k]  16.8MB
__device__ float  g_bpk[NG];
__device__ __half g_axh[(size_t)T_STEPS * B_SZ * 1024];     // x hi split  33.5MB
__device__ __half g_axl[(size_t)T_STEPS * B_SZ * 1024];     // x lo split  33.5MB
__device__ float  g_Xpre[(size_t)T_STEPS * B_SZ * NG];      // 268MB
__device__ __half g_ah[2][B_SZ * H_SZ];                     // h hi split, dbl-buffered
__device__ __half g_al[2][B_SZ * H_SZ];                     // h lo split
__device__ float  g_c[B_SZ * H_SZ];

#define U32(x) (*reinterpret_cast<const unsigned*>(&(x)))

__device__ __forceinline__ void mma16816(float* c, const unsigned* a, const unsigned* b) {
    asm volatile(
        "mma.sync.aligned.m16n8k16.row.col.f32.f16.f16.f32 "
        "{%0,%1,%2,%3}, {%4,%5,%6,%7}, {%8,%9}, {%0,%1,%2,%3};\n"
        : "+f"(c[0]), "+f"(c[1]), "+f"(c[2]), "+f"(c[3])
        : "r"(a[0]), "r"(a[1]), "r"(a[2]), "r"(a[3]), "r"(b[0]), "r"(b[1]));
}

__device__ __forceinline__ void cp16(void* smem_dst, const void* gsrc) {
    unsigned s = (unsigned)__cvta_generic_to_shared(smem_dst);
    asm volatile("cp.async.cg.shared.global [%0], [%1], 16;\n" :: "r"(s), "l"(gsrc));
}

// ---------------------------------------------------------------------------
// Pack weights: split fp16 hi/lo, n-major [n][k] layouts.
//   Wxpk[s][n'][k]  n' = j*4+g (gate-interleaved)
//   Whpk[blk][s][jl*4+g][k]  blk = j>>3, jl = j&7   (per-block gathered)
// ---------------------------------------------------------------------------
__global__ void pack_weights(const float* __restrict__ Wff, const float* __restrict__ bff,
                             const float* __restrict__ Wii, const float* __restrict__ bii,
                             const float* __restrict__ Wgg, const float* __restrict__ bgg,
                             const float* __restrict__ Woo, const float* __restrict__ boo) {
    int idx = blockIdx.x * blockDim.x + threadIdx.x;
    if (idx >= 1024 * 1024) return;
    int j = idx >> 10, k = idx & 1023;
    const float* Wm[4] = {Wff, Wii, Wgg, Woo};
    const float* bm[4] = {bff, bii, bgg, boo};
#pragma unroll
    for (int g = 0; g < 4; g++) {
        float vx = Wm[g][(size_t)j * 2048 + k];
        float vh = Wm[g][(size_t)j * 2048 + 1024 + k];
        __half xh = __float2half_rn(vx);
        __half xl = __float2half_rn(vx - __half2float(xh));
        __half hh = __float2half_rn(vh);
        __half hl = __float2half_rn(vh - __half2float(hh));
        int np = j * 4 + g;
        g_Wxpk[(size_t)np * 1024 + k]          = xh;
        g_Wxpk[(size_t)(NG + np) * 1024 + k]   = xl;
        int b = j >> 3, jl = j & 7, n32 = jl * 4 + g;
        g_Whpk[(((size_t)b * 2 + 0) * 32 + n32) * 1024 + k] = hh;
        g_Whpk[(((size_t)b * 2 + 1) * 32 + n32) * 1024 + k] = hl;
        if (k == 0) g_bpk[np] = bm[g][j];
    }
}

__global__ void convert_x(const float* __restrict__ x) {
    int idx = blockIdx.x * blockDim.x + threadIdx.x;
    if (idx >= T_STEPS * B_SZ * 1024) return;
    float v = x[idx];
    __half h = __float2half_rn(v);
    g_axh[idx] = h;
    g_axl[idx] = __float2half_rn(v - __half2float(h));
}

__global__ void zero_state() {
    int i = blockIdx.x * blockDim.x + threadIdx.x;
    if (i < B_SZ * H_SZ) {
        g_ah[0][i] = __float2half_rn(0.f);
        g_al[0][i] = __float2half_rn(0.f);
        g_c[i] = 0.f;
    }
}

// ---------------------------------------------------------------------------
// Precompute: Xpre[16384, 4096] = [xh|xl] GEMM with compensated 3-pass split.
// Block tile 128x128, BK=32, 8 warps (warp tile 64x32), cp.async staging.
// ---------------------------------------------------------------------------
__global__ __launch_bounds__(256, 2) void gemm_xpre() {
    __shared__ __half Axh[128][40];
    __shared__ __half Axl[128][40];
    __shared__ __half Whs[128][40];
    __shared__ __half Wls[128][40];

    const int tid = threadIdx.x;
    const int lane = tid & 31, w = tid >> 5;
    const int grp = lane >> 2, t4 = lane & 3;
    const int wm = w >> 2, wn = w & 3;       // 2 x 4 warp grid
    const int nb = blockIdx.x, mb = blockIdx.y;

    float acc[4][4][4];
#pragma unroll
    for (int m = 0; m < 4; m++)
#pragma unroll
        for (int n = 0; n < 4; n++)
#pragma unroll
            for (int i = 0; i < 4; i++) acc[m][n][i] = 0.f;

    for (int kc = 0; kc < 32; ++kc) {
        const int k0 = kc * 32;
        __syncthreads();
#pragma unroll
        for (int i = 0; i < 2; i++) {
            int e = tid + i * 256;
            int row = e >> 2, cg = e & 3;
            cp16(&Axh[row][cg * 8], &g_axh[(size_t)(mb * 128 + row) * 1024 + k0 + cg * 8]);
            cp16(&Axl[row][cg * 8], &g_axl[(size_t)(mb * 128 + row) * 1024 + k0 + cg * 8]);
            cp16(&Whs[row][cg * 8], &g_Wxpk[(size_t)(nb * 128 + row) * 1024 + k0 + cg * 8]);
            cp16(&Wls[row][cg * 8], &g_Wxpk[(size_t)(NG + nb * 128 + row) * 1024 + k0 + cg * 8]);
        }
        asm volatile("cp.async.commit_group;\n");
        asm volatile("cp.async.wait_group 0;\n");
        __syncthreads();

#pragma unroll
        for (int kk = 0; kk < 32; kk += 16) {
            unsigned af[4][4], bf2[4][2];
            const int c = kk + 2 * t4;
            // A <- xh
#pragma unroll
            for (int m = 0; m < 4; m++) {
                int r = wm * 64 + m * 16 + grp;
                af[m][0] = U32(Axh[r][c]);     af[m][1] = U32(Axh[r + 8][c]);
                af[m][2] = U32(Axh[r][c + 8]); af[m][3] = U32(Axh[r + 8][c + 8]);
            }
            // B <- Wh : pass (xh, Wh)
#pragma unroll
            for (int n = 0; n < 4; n++) {
                int rn = wn * 32 + n * 8 + grp;
                bf2[n][0] = U32(Whs[rn][c]); bf2[n][1] = U32(Whs[rn][c + 8]);
            }
#pragma unroll
            for (int m = 0; m < 4; m++)
#pragma unroll
                for (int n = 0; n < 4; n++) mma16816(acc[m][n], af[m], bf2[n]);
            // B <- Wl : pass (xh, Wl)
#pragma unroll
            for (int n = 0; n < 4; n++) {
                int rn = wn * 32 + n * 8 + grp;
                bf2[n][0] = U32(Wls[rn][c]); bf2[n][1] = U32(Wls[rn][c + 8]);
            }
#pragma unroll
            for (int m = 0; m < 4; m++)
#pragma unroll
                for (int n = 0; n < 4; n++) mma16816(acc[m][n], af[m], bf2[n]);
            // A <- xl, B <- Wh : pass (xl, Wh)
#pragma unroll
            for (int m = 0; m < 4; m++) {
                int r = wm * 64 + m * 16 + grp;
                af[m][0] = U32(Axl[r][c]);     af[m][1] = U32(Axl[r + 8][c]);
                af[m][2] = U32(Axl[r][c + 8]); af[m][3] = U32(Axl[r + 8][c + 8]);
            }
#pragma unroll
            for (int n = 0; n < 4; n++) {
                int rn = wn * 32 + n * 8 + grp;
                bf2[n][0] = U32(Whs[rn][c]); bf2[n][1] = U32(Whs[rn][c + 8]);
            }
#pragma unroll
            for (int m = 0; m < 4; m++)
#pragma unroll
                for (int n = 0; n < 4; n++) mma16816(acc[m][n], af[m], bf2[n]);
        }
    }

    // epilogue: + bias, write fp32
#pragma unroll
    for (int m = 0; m < 4; m++) {
        int r = mb * 128 + wm * 64 + m * 16 + grp;
#pragma unroll
        for (int n = 0; n < 4; n++) {
            int cn = nb * 128 + wn * 32 + n * 8 + 2 * t4;
            float b0 = __ldg(&g_bpk[cn]), b1 = __ldg(&g_bpk[cn + 1]);
            float2 v0 = make_float2(acc[m][n][0] + b0, acc[m][n][1] + b1);
            float2 v1 = make_float2(acc[m][n][2] + b0, acc[m][n][3] + b1);
            *reinterpret_cast<float2*>(&g_Xpre[(size_t)r * NG + cn]) = v0;
            *reinterpret_cast<float2*>(&g_Xpre[(size_t)(r + 8) * NG + cn]) = v1;
        }
    }
}

// ---------------------------------------------------------------------------
// One LSTM step. 128 blocks x 256 threads. Block tile M=64(batch) x N=32
// (8 hidden units x 4 gates, gate-interleaved). K=1024 x 3 compensated passes.
// Register-staged smem pipeline; smem z-exchange epilogue.
// ---------------------------------------------------------------------------
__global__ __launch_bounds__(256) void lstm_step(int t, float* __restrict__ out) {
    __shared__ __half Ah[64][40];
    __shared__ __half Al[64][40];
    __shared__ __half Ws[2][32][40];
    __shared__ float  zsm[64][36];

    const int tid = threadIdx.x;
    const int lane = tid & 31, w = tid >> 5;
    const int grp = lane >> 2, t4 = lane & 3;
    const int mf = w & 3, np = w >> 2;       // 8 warps: 4 m-frags x 2 n-pairs
    const int hb8 = blockIdx.x * 8;

    const __half* __restrict__ ah_in = g_ah[t & 1];
    const __half* __restrict__ al_in = g_al[t & 1];
    __half* __restrict__ ah_out = g_ah[(t + 1) & 1];
    __half* __restrict__ al_out = g_al[(t + 1) & 1];
    const float* __restrict__ xpre_t = g_Xpre + (size_t)t * (B_SZ * NG);
    float* __restrict__ out_t = out + (size_t)t * (B_SZ * H_SZ);

    // staging assignments
    const int arow = tid >> 2, acg = tid & 3;                   // A: 64 rows x 4 f4
    const int ws_ = tid >> 7, wrow = (tid >> 2) & 31, wcg = tid & 3;
    const size_t wbase = (((size_t)blockIdx.x * 2 + ws_) * 32 + wrow) * 1024;

    float acc[2][4] = {{0.f, 0.f, 0.f, 0.f}, {0.f, 0.f, 0.f, 0.f}};

    float4 ra = *reinterpret_cast<const float4*>(&ah_in[arow * 1024 + acg * 8]);
    float4 rb = *reinterpret_cast<const float4*>(&al_in[arow * 1024 + acg * 8]);
    float4 rw = *reinterpret_cast<const float4*>(&g_Whpk[wbase + wcg * 8]);

    for (int kc = 0; kc < 32; kc++) {
        __syncthreads();
        *reinterpret_cast<float4*>(&Ah[arow][acg * 8]) = ra;
        *reinterpret_cast<float4*>(&Al[arow][acg * 8]) = rb;
        *reinterpret_cast<float4*>(&Ws[ws_][wrow][wcg * 8]) = rw;
        __syncthreads();
        if (kc + 1 < 32) {
            int k0 = (kc + 1) * 32;
            ra = *reinterpret_cast<const float4*>(&ah_in[arow * 1024 + k0 + acg * 8]);
            rb = *reinterpret_cast<const float4*>(&al_in[arow * 1024 + k0 + acg * 8]);
            rw = *reinterpret_cast<const float4*>(&g_Whpk[wbase + k0 + wcg * 8]);
        }
#pragma unroll
        for (int kk = 0; kk < 32; kk += 16) {
            const int r0 = mf * 16 + grp, c0 = kk + 2 * t4;
            unsigned a_h[4], a_l[4], bh[2][2], bl[2][2];
            a_h[0] = U32(Ah[r0][c0]);     a_h[1] = U32(Ah[r0 + 8][c0]);
            a_h[2] = U32(Ah[r0][c0 + 8]); a_h[3] = U32(Ah[r0 + 8][c0 + 8]);
            a_l[0] = U32(Al[r0][c0]);     a_l[1] = U32(Al[r0 + 8][c0]);
            a_l[2] = U32(Al[r0][c0 + 8]); a_l[3] = U32(Al[r0 + 8][c0 + 8]);
#pragma unroll
            for (int q = 0; q < 2; q++) {
                int n0 = (np * 2 + q) * 8 + grp;
                bh[q][0] = U32(Ws[0][n0][c0]); bh[q][1] = U32(Ws[0][n0][c0 + 8]);
                bl[q][0] = U32(Ws[1][n0][c0]); bl[q][1] = U32(Ws[1][n0][c0 + 8]);
            }
            mma16816(acc[0], a_h, bh[0]); mma16816(acc[1], a_h, bh[1]);
            mma16816(acc[0], a_l, bh[0]); mma16816(acc[1], a_l, bh[1]);
            mma16816(acc[0], a_h, bl[0]); mma16816(acc[1], a_h, bl[1]);
        }
    }

    // dump z tiles to smem for gate-aligned epilogue
#pragma unroll
    for (int q = 0; q < 2; q++) {
        int n0 = (np * 2 + q) * 8 + 2 * t4;
        int r0 = mf * 16 + grp;
        zsm[r0][n0]         = acc[q][0];
        zsm[r0][n0 + 1]     = acc[q][1];
        zsm[r0 + 8][n0]     = acc[q][2];
        zsm[r0 + 8][n0 + 1] = acc[q][3];
    }
    __syncthreads();

#pragma unroll
    for (int i = 0; i < 2; i++) {
        int p = tid + i * 256;
        int b = p >> 3, jl = p & 7;
        int hb = hb8 + jl;
        float4 xp = *reinterpret_cast<const float4*>(&xpre_t[((size_t)(b << 10) + hb) << 2]);
        float zf = zsm[b][jl * 4 + 0] + xp.x;
        float zi = zsm[b][jl * 4 + 1] + xp.y;
        float zg = zsm[b][jl * 4 + 2] + xp.z;
        float zo = zsm[b][jl * 4 + 3] + xp.w;
        float f  = 1.f / (1.f + expf(-zf));
        float ig = 1.f / (1.f + expf(-zi));
        float gg = tanhf(zg);
        float oo = 1.f / (1.f + expf(-zo));
        int idx = (b << 10) + hb;
        float cn = f * g_c[idx] + ig * gg;
        g_c[idx] = cn;
        float hn = oo * tanhf(cn);
        out_t[idx] = hn;
        __half hh = __float2half_rn(hn);
        ah_out[idx] = hh;
        al_out[idx] = __float2half_rn(hn - __half2float(hh));
    }
}

__global__ void write_tail(const float* __restrict__ out_last, float* __restrict__ out_tail) {
    int i = blockIdx.x * blockDim.x + threadIdx.x;
    if (i < B_SZ * H_SZ) {
        out_tail[i] = out_last[i];                 // hx = h_{T-1} (exact fp32 copy)
        out_tail[B_SZ * H_SZ + i] = g_c[i];        // cx
    }
}

extern "C" void kernel_launch(void* const* d_in, const int* in_sizes, int n_in,
                              void* d_out, int out_size) {
    const float* inputs = (const float*)d_in[0];
    const float* Wf = (const float*)d_in[1];
    const float* bf = (const float*)d_in[2];
    const float* Wi = (const float*)d_in[3];
    const float* bi = (const float*)d_in[4];
    const float* Wg = (const float*)d_in[5];
    const float* bg = (const float*)d_in[6];
    const float* Wo = (const float*)d_in[7];
    const float* bo = (const float*)d_in[8];
    float* out = (float*)d_out;

    pack_weights<<<(1024 * 1024 + 255) / 256, 256>>>(Wf, bf, Wi, bi, Wg, bg, Wo, bo);
    convert_x<<<(T_STEPS * B_SZ * 1024 + 255) / 256, 256>>>(inputs);
    zero_state<<<(B_SZ * H_SZ + 255) / 256, 256>>>();

    dim3 g1(NG / 128, (T_STEPS * B_SZ) / 128);
    gemm_xpre<<<g1, 256>>>();

    for (int t = 0; t < T_STEPS; t++) {
        lstm_step<<<128, 256>>>(t, out);
    }

    const int tail_needed = T_STEPS * B_SZ * H_SZ + 2 * B_SZ * H_SZ;
    if (out_size >= tail_needed) {
        write_tail<<<(B_SZ * H_SZ + 255) / 256, 256>>>(
            out + (size_t)(T_STEPS - 1) * B_SZ * H_SZ,
            out + (size_t)T_STEPS * B_SZ * H_SZ);
    }
}

// round 4
// speedup vs baseline: 2.8142x; 1.2966x over previous
#include <cuda_runtime.h>
#include <cuda_fp16.h>
#include <math.h>

#define T_STEPS 256
#define B_SZ    64
#define H_SZ    1024
#define NG      4096   // 4*H
#define WPAD    1032   // padded k-stride for smem-resident weights (bank-safe)

// ---------------- device-global scratch (allocation-free contract) ---------
__device__ __half g_Wxpk[(size_t)2 * NG * 1024];            // [s][n'=j*4+g][k]
__device__ __half g_Whpk[(size_t)128 * 2 * 32 * 1024];      // [blk][s][n32][k]
__device__ float  g_bpk[NG];
__device__ __half g_axh[(size_t)T_STEPS * B_SZ * 1024];
__device__ __half g_axl[(size_t)T_STEPS * B_SZ * 1024];
__device__ float  g_Xpre[(size_t)T_STEPS * B_SZ * NG];
__device__ __half g_ah[2][B_SZ * H_SZ];
__device__ __half g_al[2][B_SZ * H_SZ];
__device__ unsigned g_barc;

#define U32(x) (*reinterpret_cast<const unsigned*>(&(x)))

__device__ __forceinline__ void mma16816(float* c, const unsigned* a, const unsigned* b) {
    asm volatile(
        "mma.sync.aligned.m16n8k16.row.col.f32.f16.f16.f32 "
        "{%0,%1,%2,%3}, {%4,%5,%6,%7}, {%8,%9}, {%0,%1,%2,%3};\n"
        : "+f"(c[0]), "+f"(c[1]), "+f"(c[2]), "+f"(c[3])
        : "r"(a[0]), "r"(a[1]), "r"(a[2]), "r"(a[3]), "r"(b[0]), "r"(b[1]));
}

__device__ __forceinline__ void cp16(void* smem_dst, const void* gsrc) {
    unsigned s = (unsigned)__cvta_generic_to_shared(smem_dst);
    asm volatile("cp.async.cg.shared.global [%0], [%1], 16;\n" :: "r"(s), "l"(gsrc));
}

__device__ __forceinline__ unsigned ldacq(const unsigned* p) {
    unsigned v;
    asm volatile("ld.acquire.gpu.global.u32 %0, [%1];" : "=r"(v) : "l"(p) : "memory");
    return v;
}

// ---------------------------------------------------------------------------
// Pack weights (split fp16 hi/lo, n-major, gate-interleaved; per-block gather
// for the recurrence).
// ---------------------------------------------------------------------------
__global__ void pack_weights(const float* __restrict__ Wff, const float* __restrict__ bff,
                             const float* __restrict__ Wii, const float* __restrict__ bii,
                             const float* __restrict__ Wgg, const float* __restrict__ bgg,
                             const float* __restrict__ Woo, const float* __restrict__ boo) {
    int idx = blockIdx.x * blockDim.x + threadIdx.x;
    if (idx >= 1024 * 1024) return;
    int j = idx >> 10, k = idx & 1023;
    const float* Wm[4] = {Wff, Wii, Wgg, Woo};
    const float* bm[4] = {bff, bii, bgg, boo};
#pragma unroll
    for (int g = 0; g < 4; g++) {
        float vx = Wm[g][(size_t)j * 2048 + k];
        float vh = Wm[g][(size_t)j * 2048 + 1024 + k];
        __half xh = __float2half_rn(vx);
        __half xl = __float2half_rn(vx - __half2float(xh));
        __half hh = __float2half_rn(vh);
        __half hl = __float2half_rn(vh - __half2float(hh));
        int np = j * 4 + g;
        g_Wxpk[(size_t)np * 1024 + k]        = xh;
        g_Wxpk[(size_t)(NG + np) * 1024 + k] = xl;
        int b = j >> 3, jl = j & 7, n32 = jl * 4 + g;
        g_Whpk[(((size_t)b * 2 + 0) * 32 + n32) * 1024 + k] = hh;
        g_Whpk[(((size_t)b * 2 + 1) * 32 + n32) * 1024 + k] = hl;
        if (k == 0) g_bpk[np] = bm[g][j];
    }
}

__global__ void convert_x(const float* __restrict__ x) {
    int idx = blockIdx.x * blockDim.x + threadIdx.x;
    if (idx >= T_STEPS * B_SZ * 1024) return;
    float v = x[idx];
    __half h = __float2half_rn(v);
    g_axh[idx] = h;
    g_axl[idx] = __float2half_rn(v - __half2float(h));
}

__global__ void zero_state() {
    int i = blockIdx.x * blockDim.x + threadIdx.x;
    if (i < B_SZ * H_SZ) {
        g_ah[0][i] = __float2half_rn(0.f);
        g_al[0][i] = __float2half_rn(0.f);
    }
    if (blockIdx.x == 0 && threadIdx.x == 0) g_barc = 0u;
}

// ---------------------------------------------------------------------------
// Precompute: Xpre = [xh|xl] @ Wx (3-pass compensated), 128x128 tile, BK=32,
// 2-stage cp.async pipeline.
// ---------------------------------------------------------------------------
#define GX_SMEM (8 * 128 * 40 * 2)   // 4 arrays x 2 stages x 128x40 halves

__device__ __forceinline__ void gx_issue(char* sm, int st, int kc, int tid, int mb, int nb) {
    __half(*Axh)[128][40] = reinterpret_cast<__half(*)[128][40]>(sm);
    __half(*Axl)[128][40] = reinterpret_cast<__half(*)[128][40]>(sm + 20480);
    __half(*Whs)[128][40] = reinterpret_cast<__half(*)[128][40]>(sm + 40960);
    __half(*Wls)[128][40] = reinterpret_cast<__half(*)[128][40]>(sm + 61440);
    const int k0 = kc * 32;
#pragma unroll
    for (int i = 0; i < 2; i++) {
        int e = tid + i * 256;
        int row = e >> 2, cg = e & 3;
        cp16(&Axh[st][row][cg * 8], &g_axh[(size_t)(mb * 128 + row) * 1024 + k0 + cg * 8]);
        cp16(&Axl[st][row][cg * 8], &g_axl[(size_t)(mb * 128 + row) * 1024 + k0 + cg * 8]);
        cp16(&Whs[st][row][cg * 8], &g_Wxpk[(size_t)(nb * 128 + row) * 1024 + k0 + cg * 8]);
        cp16(&Wls[st][row][cg * 8], &g_Wxpk[(size_t)(NG + nb * 128 + row) * 1024 + k0 + cg * 8]);
    }
    asm volatile("cp.async.commit_group;\n" ::);
}

__global__ __launch_bounds__(256, 2) void gemm_xpre() {
    extern __shared__ char sm[];
    __half(*Axh)[128][40] = reinterpret_cast<__half(*)[128][40]>(sm);
    __half(*Axl)[128][40] = reinterpret_cast<__half(*)[128][40]>(sm + 20480);
    __half(*Whs)[128][40] = reinterpret_cast<__half(*)[128][40]>(sm + 40960);
    __half(*Wls)[128][40] = reinterpret_cast<__half(*)[128][40]>(sm + 61440);

    const int tid = threadIdx.x;
    const int lane = tid & 31, w = tid >> 5;
    const int grp = lane >> 2, t4 = lane & 3;
    const int wm = w >> 2, wn = w & 3;
    const int nb = blockIdx.x, mb = blockIdx.y;

    float acc[4][4][4];
#pragma unroll
    for (int m = 0; m < 4; m++)
#pragma unroll
        for (int n = 0; n < 4; n++)
#pragma unroll
            for (int i = 0; i < 4; i++) acc[m][n][i] = 0.f;

    gx_issue(sm, 0, 0, tid, mb, nb);

    for (int kc = 0; kc < 32; ++kc) {
        const int cur = kc & 1;
        if (kc + 1 < 32) gx_issue(sm, cur ^ 1, kc + 1, tid, mb, nb);
        if (kc + 1 < 32) asm volatile("cp.async.wait_group 1;\n" ::);
        else             asm volatile("cp.async.wait_group 0;\n" ::);
        __syncthreads();

#pragma unroll
        for (int kk = 0; kk < 32; kk += 16) {
            unsigned af[4][4], bf2[4][2];
            const int c = kk + 2 * t4;
#pragma unroll
            for (int m = 0; m < 4; m++) {
                int r = wm * 64 + m * 16 + grp;
                af[m][0] = U32(Axh[cur][r][c]);     af[m][1] = U32(Axh[cur][r + 8][c]);
                af[m][2] = U32(Axh[cur][r][c + 8]); af[m][3] = U32(Axh[cur][r + 8][c + 8]);
            }
#pragma unroll
            for (int n = 0; n < 4; n++) {
                int rn = wn * 32 + n * 8 + grp;
                bf2[n][0] = U32(Whs[cur][rn][c]); bf2[n][1] = U32(Whs[cur][rn][c + 8]);
            }
#pragma unroll
            for (int m = 0; m < 4; m++)
#pragma unroll
                for (int n = 0; n < 4; n++) mma16816(acc[m][n], af[m], bf2[n]);
#pragma unroll
            for (int n = 0; n < 4; n++) {
                int rn = wn * 32 + n * 8 + grp;
                bf2[n][0] = U32(Wls[cur][rn][c]); bf2[n][1] = U32(Wls[cur][rn][c + 8]);
            }
#pragma unroll
            for (int m = 0; m < 4; m++)
#pragma unroll
                for (int n = 0; n < 4; n++) mma16816(acc[m][n], af[m], bf2[n]);
#pragma unroll
            for (int m = 0; m < 4; m++) {
                int r = wm * 64 + m * 16 + grp;
                af[m][0] = U32(Axl[cur][r][c]);     af[m][1] = U32(Axl[cur][r + 8][c]);
                af[m][2] = U32(Axl[cur][r][c + 8]); af[m][3] = U32(Axl[cur][r + 8][c + 8]);
            }
#pragma unroll
            for (int n = 0; n < 4; n++) {
                int rn = wn * 32 + n * 8 + grp;
                bf2[n][0] = U32(Whs[cur][rn][c]); bf2[n][1] = U32(Whs[cur][rn][c + 8]);
            }
#pragma unroll
            for (int m = 0; m < 4; m++)
#pragma unroll
                for (int n = 0; n < 4; n++) mma16816(acc[m][n], af[m], bf2[n]);
        }
        __syncthreads();
    }

#pragma unroll
    for (int m = 0; m < 4; m++) {
        int r = mb * 128 + wm * 64 + m * 16 + grp;
#pragma unroll
        for (int n = 0; n < 4; n++) {
            int cn = nb * 128 + wn * 32 + n * 8 + 2 * t4;
            float b0 = __ldg(&g_bpk[cn]), b1 = __ldg(&g_bpk[cn + 1]);
            float2 v0 = make_float2(acc[m][n][0] + b0, acc[m][n][1] + b1);
            float2 v1 = make_float2(acc[m][n][2] + b0, acc[m][n][3] + b1);
            *reinterpret_cast<float2*>(&g_Xpre[(size_t)r * NG + cn]) = v0;
            *reinterpret_cast<float2*>(&g_Xpre[(size_t)(r + 8) * NG + cn]) = v1;
        }
    }
}

// ---------------------------------------------------------------------------
// Persistent recurrence. 128 blocks x 256 threads, 1 block/SM. Wh slice
// resident in smem for all 256 steps; c-state in registers; monotonic atomic
// grid barrier between steps; double-buffered h staging (1 bar/chunk).
// ---------------------------------------------------------------------------
#define LS_W_OFF   0
#define LS_AH_OFF  132096                  // 64 rows x WPAD halves x 2B
#define LS_AL_OFF  (LS_AH_OFF + 10240)     // 2 x 64 x 40 halves
#define LS_Z_OFF   (LS_AL_OFF + 10240)
#define LS_SMEM    (LS_Z_OFF + 64 * 36 * 4)   // 161792 B

__global__ __launch_bounds__(256, 1) void lstm_persist(float* __restrict__ out,
                                                       float* __restrict__ out_tail) {
    extern __shared__ char sm[];
    __half(*Wsp)[WPAD] = reinterpret_cast<__half(*)[WPAD]>(sm + LS_W_OFF);   // [64][WPAD]
    __half(*Ah)[64][40] = reinterpret_cast<__half(*)[64][40]>(sm + LS_AH_OFF);
    __half(*Al)[64][40] = reinterpret_cast<__half(*)[64][40]>(sm + LS_AL_OFF);
    float(*zsm)[36]     = reinterpret_cast<float(*)[36]>(sm + LS_Z_OFF);

    const int tid = threadIdx.x;
    const int lane = tid & 31, w = tid >> 5;
    const int grp = lane >> 2, t4 = lane & 3;
    const int mf = w & 3, np = w >> 2;
    const int hb8 = blockIdx.x * 8;
    const int arow = tid >> 2, acg = tid & 3;

    // ---- load this block's Wh slice into smem once ----
    const size_t wsrc = (size_t)blockIdx.x * 65536;   // blk*2*32*1024
    for (int i = tid; i < 8192; i += 256) {
        int sn = i >> 7, kc8 = i & 127;
        *reinterpret_cast<float4*>(&Wsp[sn][kc8 * 8]) =
            *reinterpret_cast<const float4*>(&g_Whpk[wsrc + (size_t)sn * 1024 + kc8 * 8]);
    }
    __syncthreads();

    // persistent c-state: thread covers (b,jl) pairs p = tid, tid+256
    float c_reg[2] = {0.f, 0.f};

#pragma unroll 1
    for (int t = 0; t < T_STEPS; t++) {
        const __half* __restrict__ ah_in = g_ah[t & 1];
        const __half* __restrict__ al_in = g_al[t & 1];
        __half* __restrict__ ah_out = g_ah[(t + 1) & 1];
        __half* __restrict__ al_out = g_al[(t + 1) & 1];
        const float* __restrict__ xpre_t = g_Xpre + (size_t)t * (B_SZ * NG);
        float* __restrict__ out_t = out + (size_t)t * (B_SZ * H_SZ);

        // prefetch this step's xpre gate-vectors (DRAM; overlaps the k-loop)
        float4 xp[2];
#pragma unroll
        for (int i = 0; i < 2; i++) {
            int p = tid + i * 256;
            int b = p >> 3, jl = p & 7;
            xp[i] = *reinterpret_cast<const float4*>(&xpre_t[(size_t)b * NG + (hb8 + jl) * 4]);
        }

        float acc[2][4] = {{0.f, 0.f, 0.f, 0.f}, {0.f, 0.f, 0.f, 0.f}};

        // chunk 0 into buf 0
        *reinterpret_cast<float4*>(&Ah[0][arow][acg * 8]) =
            *reinterpret_cast<const float4*>(&ah_in[arow * 1024 + acg * 8]);
        *reinterpret_cast<float4*>(&Al[0][arow][acg * 8]) =
            *reinterpret_cast<const float4*>(&al_in[arow * 1024 + acg * 8]);
        __syncthreads();

#pragma unroll 1
        for (int kc = 0; kc < 32; kc++) {
            const int cur = kc & 1;
            float4 ra, rb;
            if (kc < 31) {
                int k0 = (kc + 1) * 32;
                ra = *reinterpret_cast<const float4*>(&ah_in[arow * 1024 + k0 + acg * 8]);
                rb = *reinterpret_cast<const float4*>(&al_in[arow * 1024 + k0 + acg * 8]);
            }
#pragma unroll
            for (int kk = 0; kk < 32; kk += 16) {
                const int r0 = mf * 16 + grp;
                const int c0 = kc * 32 + kk + 2 * t4;    // absolute k column in Wsp
                const int cs = kk + 2 * t4;              // column in staging buffer
                unsigned a_h[4], a_l[4], bh[2][2], bl[2][2];
                a_h[0] = U32(Ah[cur][r0][cs]);     a_h[1] = U32(Ah[cur][r0 + 8][cs]);
                a_h[2] = U32(Ah[cur][r0][cs + 8]); a_h[3] = U32(Ah[cur][r0 + 8][cs + 8]);
                a_l[0] = U32(Al[cur][r0][cs]);     a_l[1] = U32(Al[cur][r0 + 8][cs]);
                a_l[2] = U32(Al[cur][r0][cs + 8]); a_l[3] = U32(Al[cur][r0 + 8][cs + 8]);
#pragma unroll
                for (int q = 0; q < 2; q++) {
                    int n0 = (np * 2 + q) * 8 + grp;
                    bh[q][0] = U32(Wsp[n0][c0]);      bh[q][1] = U32(Wsp[n0][c0 + 8]);
                    bl[q][0] = U32(Wsp[32 + n0][c0]); bl[q][1] = U32(Wsp[32 + n0][c0 + 8]);
                }
                mma16816(acc[0], a_h, bh[0]); mma16816(acc[1], a_h, bh[1]);
                mma16816(acc[0], a_l, bh[0]); mma16816(acc[1], a_l, bh[1]);
                mma16816(acc[0], a_h, bl[0]); mma16816(acc[1], a_h, bl[1]);
            }
            if (kc < 31) {
                *reinterpret_cast<float4*>(&Ah[cur ^ 1][arow][acg * 8]) = ra;
                *reinterpret_cast<float4*>(&Al[cur ^ 1][arow][acg * 8]) = rb;
            }
            __syncthreads();
        }

        // z exchange
#pragma unroll
        for (int q = 0; q < 2; q++) {
            int n0 = (np * 2 + q) * 8 + 2 * t4;
            int r0 = mf * 16 + grp;
            zsm[r0][n0]         = acc[q][0];
            zsm[r0][n0 + 1]     = acc[q][1];
            zsm[r0 + 8][n0]     = acc[q][2];
            zsm[r0 + 8][n0 + 1] = acc[q][3];
        }
        __syncthreads();

        // gate math + state update
#pragma unroll
        for (int i = 0; i < 2; i++) {
            int p = tid + i * 256;
            int b = p >> 3, jl = p & 7;
            int hb = hb8 + jl;
            float zf = zsm[b][jl * 4 + 0] + xp[i].x;
            float zi = zsm[b][jl * 4 + 1] + xp[i].y;
            float zg = zsm[b][jl * 4 + 2] + xp[i].z;
            float zo = zsm[b][jl * 4 + 3] + xp[i].w;
            float f  = 1.f / (1.f + expf(-zf));
            float ig = 1.f / (1.f + expf(-zi));
            float gg = tanhf(zg);
            float oo = 1.f / (1.f + expf(-zo));
            int idx = (b << 10) + hb;
            float cn = f * c_reg[i] + ig * gg;
            c_reg[i] = cn;
            float hn = oo * tanhf(cn);
            out_t[idx] = hn;
            __half hh = __float2half_rn(hn);
            ah_out[idx] = hh;
            al_out[idx] = __float2half_rn(hn - __half2float(hh));
            if (t == T_STEPS - 1 && out_tail) {
                out_tail[idx] = hn;
                out_tail[B_SZ * H_SZ + idx] = cn;
            }
        }

        // grid barrier (skip after last step)
        if (t < T_STEPS - 1) {
            __threadfence();
            __syncthreads();
            if (tid == 0) {
                atomicAdd(&g_barc, 1u);
                unsigned target = (unsigned)(t + 1) * (unsigned)gridDim.x;
                while (ldacq(&g_barc) < target) { }
            }
            __syncthreads();
        }
    }
}

extern "C" void kernel_launch(void* const* d_in, const int* in_sizes, int n_in,
                              void* d_out, int out_size) {
    const float* inputs = (const float*)d_in[0];
    const float* Wf = (const float*)d_in[1];
    const float* bf = (const float*)d_in[2];
    const float* Wi = (const float*)d_in[3];
    const float* bi = (const float*)d_in[4];
    const float* Wg = (const float*)d_in[5];
    const float* bg = (const float*)d_in[6];
    const float* Wo = (const float*)d_in[7];
    const float* bo = (const float*)d_in[8];
    float* out = (float*)d_out;

    cudaFuncSetAttribute(gemm_xpre, cudaFuncAttributeMaxDynamicSharedMemorySize, GX_SMEM);
    cudaFuncSetAttribute(lstm_persist, cudaFuncAttributeMaxDynamicSharedMemorySize, LS_SMEM);

    pack_weights<<<(1024 * 1024 + 255) / 256, 256>>>(Wf, bf, Wi, bi, Wg, bg, Wo, bo);
    convert_x<<<(T_STEPS * B_SZ * 1024 + 255) / 256, 256>>>(inputs);
    zero_state<<<(B_SZ * H_SZ + 255) / 256, 256>>>();

    dim3 g1(NG / 128, (T_STEPS * B_SZ) / 128);
    gemm_xpre<<<g1, 256, GX_SMEM>>>();

    const int tail_needed = T_STEPS * B_SZ * H_SZ + 2 * B_SZ * H_SZ;
    float* out_tail = (out_size >= tail_needed) ? out + (size_t)T_STEPS * B_SZ * H_SZ : nullptr;
    lstm_persist<<<128, 256, LS_SMEM>>>(out, out_tail);
}

// round 5
// speedup vs baseline: 2.8209x; 1.0024x over previous
#include <cuda_runtime.h>
#include <cuda_fp16.h>
#include <math.h>

#define T_STEPS 256
#define B_SZ    64
#define H_SZ    1024
#define NG      4096   // 4*H
#define WPAD    1032   // padded k-stride for smem-resident weights (bank-safe)

// ---------------- device-global scratch (allocation-free contract) ---------
__device__ __half g_Wxpk[(size_t)2 * NG * 1024];            // [s][n'=j*4+g][k]
__device__ __half g_Whpk[(size_t)128 * 2 * 32 * 1024];      // [blk][s][n32][k]
__device__ float  g_bpk[NG];
__device__ __half g_axh[(size_t)T_STEPS * B_SZ * 1024];
__device__ __half g_axl[(size_t)T_STEPS * B_SZ * 1024];
__device__ float  g_Xpre[(size_t)T_STEPS * B_SZ * NG];
__device__ __half g_ah[2][B_SZ * H_SZ];
__device__ __half g_al[2][B_SZ * H_SZ];
__device__ unsigned g_barc;

#define U32(x) (*reinterpret_cast<const unsigned*>(&(x)))

__device__ __forceinline__ void mma16816(float* c, const unsigned* a, const unsigned* b) {
    asm volatile(
        "mma.sync.aligned.m16n8k16.row.col.f32.f16.f16.f32 "
        "{%0,%1,%2,%3}, {%4,%5,%6,%7}, {%8,%9}, {%0,%1,%2,%3};\n"
        : "+f"(c[0]), "+f"(c[1]), "+f"(c[2]), "+f"(c[3])
        : "r"(a[0]), "r"(a[1]), "r"(a[2]), "r"(a[3]), "r"(b[0]), "r"(b[1]));
}

__device__ __forceinline__ void cp16(void* smem_dst, const void* gsrc) {
    unsigned s = (unsigned)__cvta_generic_to_shared(smem_dst);
    asm volatile("cp.async.cg.shared.global [%0], [%1], 16;\n" :: "r"(s), "l"(gsrc));
}

__device__ __forceinline__ unsigned ldacq(const unsigned* p) {
    unsigned v;
    asm volatile("ld.acquire.gpu.global.u32 %0, [%1];" : "=r"(v) : "l"(p) : "memory");
    return v;
}

// ---------------------------------------------------------------------------
// Pack weights (split fp16 hi/lo, n-major, gate-interleaved; per-block gather
// for the recurrence).
// ---------------------------------------------------------------------------
__global__ void pack_weights(const float* __restrict__ Wff, const float* __restrict__ bff,
                             const float* __restrict__ Wii, const float* __restrict__ bii,
                             const float* __restrict__ Wgg, const float* __restrict__ bgg,
                             const float* __restrict__ Woo, const float* __restrict__ boo) {
    int idx = blockIdx.x * blockDim.x + threadIdx.x;
    if (idx >= 1024 * 1024) return;
    int j = idx >> 10, k = idx & 1023;
    const float* Wm[4] = {Wff, Wii, Wgg, Woo};
    const float* bm[4] = {bff, bii, bgg, boo};
#pragma unroll
    for (int g = 0; g < 4; g++) {
        float vx = Wm[g][(size_t)j * 2048 + k];
        float vh = Wm[g][(size_t)j * 2048 + 1024 + k];
        __half xh = __float2half_rn(vx);
        __half xl = __float2half_rn(vx - __half2float(xh));
        __half hh = __float2half_rn(vh);
        __half hl = __float2half_rn(vh - __half2float(hh));
        int np = j * 4 + g;
        g_Wxpk[(size_t)np * 1024 + k]        = xh;
        g_Wxpk[(size_t)(NG + np) * 1024 + k] = xl;
        int b = j >> 3, jl = j & 7, n32 = jl * 4 + g;
        g_Whpk[(((size_t)b * 2 + 0) * 32 + n32) * 1024 + k] = hh;
        g_Whpk[(((size_t)b * 2 + 1) * 32 + n32) * 1024 + k] = hl;
        if (k == 0) g_bpk[np] = bm[g][j];
    }
}

__global__ void convert_x(const float* __restrict__ x) {
    int idx = blockIdx.x * blockDim.x + threadIdx.x;
    if (idx >= T_STEPS * B_SZ * 1024) return;
    float v = x[idx];
    __half h = __float2half_rn(v);
    g_axh[idx] = h;
    g_axl[idx] = __float2half_rn(v - __half2float(h));
}

__global__ void zero_state() {
    int i = blockIdx.x * blockDim.x + threadIdx.x;
    if (i < B_SZ * H_SZ) {
        g_ah[0][i] = __float2half_rn(0.f);
        g_al[0][i] = __float2half_rn(0.f);
    }
    if (blockIdx.x == 0 && threadIdx.x == 0) g_barc = 0u;
}

// ---------------------------------------------------------------------------
// Precompute: Xpre = [xh|xl] @ Wx (3-pass compensated), 128x128 tile, BK=32,
// 2-stage cp.async pipeline.
// ---------------------------------------------------------------------------
#define GX_SMEM (8 * 128 * 40 * 2)   // 4 arrays x 2 stages x 128x40 halves

__device__ __forceinline__ void gx_issue(char* sm, int st, int kc, int tid, int mb, int nb) {
    __half(*Axh)[128][40] = reinterpret_cast<__half(*)[128][40]>(sm);
    __half(*Axl)[128][40] = reinterpret_cast<__half(*)[128][40]>(sm + 20480);
    __half(*Whs)[128][40] = reinterpret_cast<__half(*)[128][40]>(sm + 40960);
    __half(*Wls)[128][40] = reinterpret_cast<__half(*)[128][40]>(sm + 61440);
    const int k0 = kc * 32;
#pragma unroll
    for (int i = 0; i < 2; i++) {
        int e = tid + i * 256;
        int row = e >> 2, cg = e & 3;
        cp16(&Axh[st][row][cg * 8], &g_axh[(size_t)(mb * 128 + row) * 1024 + k0 + cg * 8]);
        cp16(&Axl[st][row][cg * 8], &g_axl[(size_t)(mb * 128 + row) * 1024 + k0 + cg * 8]);
        cp16(&Whs[st][row][cg * 8], &g_Wxpk[(size_t)(nb * 128 + row) * 1024 + k0 + cg * 8]);
        cp16(&Wls[st][row][cg * 8], &g_Wxpk[(size_t)(NG + nb * 128 + row) * 1024 + k0 + cg * 8]);
    }
    asm volatile("cp.async.commit_group;\n" ::);
}

__global__ __launch_bounds__(256, 2) void gemm_xpre() {
    extern __shared__ char sm[];
    __half(*Axh)[128][40] = reinterpret_cast<__half(*)[128][40]>(sm);
    __half(*Axl)[128][40] = reinterpret_cast<__half(*)[128][40]>(sm + 20480);
    __half(*Whs)[128][40] = reinterpret_cast<__half(*)[128][40]>(sm + 40960);
    __half(*Wls)[128][40] = reinterpret_cast<__half(*)[128][40]>(sm + 61440);

    const int tid = threadIdx.x;
    const int lane = tid & 31, w = tid >> 5;
    const int grp = lane >> 2, t4 = lane & 3;
    const int wm = w >> 2, wn = w & 3;
    const int nb = blockIdx.x, mb = blockIdx.y;

    float acc[4][4][4];
#pragma unroll
    for (int m = 0; m < 4; m++)
#pragma unroll
        for (int n = 0; n < 4; n++)
#pragma unroll
            for (int i = 0; i < 4; i++) acc[m][n][i] = 0.f;

    gx_issue(sm, 0, 0, tid, mb, nb);

    for (int kc = 0; kc < 32; ++kc) {
        const int cur = kc & 1;
        if (kc + 1 < 32) gx_issue(sm, cur ^ 1, kc + 1, tid, mb, nb);
        if (kc + 1 < 32) asm volatile("cp.async.wait_group 1;\n" ::);
        else             asm volatile("cp.async.wait_group 0;\n" ::);
        __syncthreads();

#pragma unroll
        for (int kk = 0; kk < 32; kk += 16) {
            unsigned af[4][4], bf2[4][2];
            const int c = kk + 2 * t4;
#pragma unroll
            for (int m = 0; m < 4; m++) {
                int r = wm * 64 + m * 16 + grp;
                af[m][0] = U32(Axh[cur][r][c]);     af[m][1] = U32(Axh[cur][r + 8][c]);
                af[m][2] = U32(Axh[cur][r][c + 8]); af[m][3] = U32(Axh[cur][r + 8][c + 8]);
            }
#pragma unroll
            for (int n = 0; n < 4; n++) {
                int rn = wn * 32 + n * 8 + grp;
                bf2[n][0] = U32(Whs[cur][rn][c]); bf2[n][1] = U32(Whs[cur][rn][c + 8]);
            }
#pragma unroll
            for (int m = 0; m < 4; m++)
#pragma unroll
                for (int n = 0; n < 4; n++) mma16816(acc[m][n], af[m], bf2[n]);
#pragma unroll
            for (int n = 0; n < 4; n++) {
                int rn = wn * 32 + n * 8 + grp;
                bf2[n][0] = U32(Wls[cur][rn][c]); bf2[n][1] = U32(Wls[cur][rn][c + 8]);
            }
#pragma unroll
            for (int m = 0; m < 4; m++)
#pragma unroll
                for (int n = 0; n < 4; n++) mma16816(acc[m][n], af[m], bf2[n]);
#pragma unroll
            for (int m = 0; m < 4; m++) {
                int r = wm * 64 + m * 16 + grp;
                af[m][0] = U32(Axl[cur][r][c]);     af[m][1] = U32(Axl[cur][r + 8][c]);
                af[m][2] = U32(Axl[cur][r][c + 8]); af[m][3] = U32(Axl[cur][r + 8][c + 8]);
            }
#pragma unroll
            for (int n = 0; n < 4; n++) {
                int rn = wn * 32 + n * 8 + grp;
                bf2[n][0] = U32(Whs[cur][rn][c]); bf2[n][1] = U32(Whs[cur][rn][c + 8]);
            }
#pragma unroll
            for (int m = 0; m < 4; m++)
#pragma unroll
                for (int n = 0; n < 4; n++) mma16816(acc[m][n], af[m], bf2[n]);
        }
        __syncthreads();
    }

#pragma unroll
    for (int m = 0; m < 4; m++) {
        int r = mb * 128 + wm * 64 + m * 16 + grp;
#pragma unroll
        for (int n = 0; n < 4; n++) {
            int cn = nb * 128 + wn * 32 + n * 8 + 2 * t4;
            float b0 = __ldg(&g_bpk[cn]), b1 = __ldg(&g_bpk[cn + 1]);
            float2 v0 = make_float2(acc[m][n][0] + b0, acc[m][n][1] + b1);
            float2 v1 = make_float2(acc[m][n][2] + b0, acc[m][n][3] + b1);
            *reinterpret_cast<float2*>(&g_Xpre[(size_t)r * NG + cn]) = v0;
            *reinterpret_cast<float2*>(&g_Xpre[(size_t)(r + 8) * NG + cn]) = v1;
        }
    }
}

// ---------------------------------------------------------------------------
// Persistent recurrence. 128 blocks x 256 threads, 1 block/SM. Wh slice
// resident in smem for all 256 steps; c-state in registers; monotonic atomic
// grid barrier between steps; double-buffered h staging (1 bar/chunk).
// ---------------------------------------------------------------------------
#define LS_W_OFF   0
#define LS_AH_OFF  132096                  // 64 rows x WPAD halves x 2B
#define LS_AL_OFF  (LS_AH_OFF + 10240)     // 2 x 64 x 40 halves
#define LS_Z_OFF   (LS_AL_OFF + 10240)
#define LS_SMEM    (LS_Z_OFF + 64 * 36 * 4)   // 161792 B

__global__ __launch_bounds__(256, 1) void lstm_persist(float* __restrict__ out,
                                                       float* __restrict__ out_tail) {
    extern __shared__ char sm[];
    __half(*Wsp)[WPAD] = reinterpret_cast<__half(*)[WPAD]>(sm + LS_W_OFF);   // [64][WPAD]
    __half(*Ah)[64][40] = reinterpret_cast<__half(*)[64][40]>(sm + LS_AH_OFF);
    __half(*Al)[64][40] = reinterpret_cast<__half(*)[64][40]>(sm + LS_AL_OFF);
    float(*zsm)[36]     = reinterpret_cast<float(*)[36]>(sm + LS_Z_OFF);

    const int tid = threadIdx.x;
    const int lane = tid & 31, w = tid >> 5;
    const int grp = lane >> 2, t4 = lane & 3;
    const int mf = w & 3, np = w >> 2;
    const int hb8 = blockIdx.x * 8;
    const int arow = tid >> 2, acg = tid & 3;

    // ---- load this block's Wh slice into smem once ----
    const size_t wsrc = (size_t)blockIdx.x * 65536;   // blk*2*32*1024
    for (int i = tid; i < 8192; i += 256) {
        int sn = i >> 7, kc8 = i & 127;
        *reinterpret_cast<float4*>(&Wsp[sn][kc8 * 8]) =
            *reinterpret_cast<const float4*>(&g_Whpk[wsrc + (size_t)sn * 1024 + kc8 * 8]);
    }
    __syncthreads();

    // persistent c-state: thread covers (b,jl) pairs p = tid, tid+256
    float c_reg[2] = {0.f, 0.f};

#pragma unroll 1
    for (int t = 0; t < T_STEPS; t++) {
        const __half* __restrict__ ah_in = g_ah[t & 1];
        const __half* __restrict__ al_in = g_al[t & 1];
        __half* __restrict__ ah_out = g_ah[(t + 1) & 1];
        __half* __restrict__ al_out = g_al[(t + 1) & 1];
        const float* __restrict__ xpre_t = g_Xpre + (size_t)t * (B_SZ * NG);
        float* __restrict__ out_t = out + (size_t)t * (B_SZ * H_SZ);

        // prefetch this step's xpre gate-vectors (DRAM; overlaps the k-loop)
        float4 xp[2];
#pragma unroll
        for (int i = 0; i < 2; i++) {
            int p = tid + i * 256;
            int b = p >> 3, jl = p & 7;
            xp[i] = *reinterpret_cast<const float4*>(&xpre_t[(size_t)b * NG + (hb8 + jl) * 4]);
        }

        float acc[2][4] = {{0.f, 0.f, 0.f, 0.f}, {0.f, 0.f, 0.f, 0.f}};

        // chunk 0 into buf 0
        *reinterpret_cast<float4*>(&Ah[0][arow][acg * 8]) =
            *reinterpret_cast<const float4*>(&ah_in[arow * 1024 + acg * 8]);
        *reinterpret_cast<float4*>(&Al[0][arow][acg * 8]) =
            *reinterpret_cast<const float4*>(&al_in[arow * 1024 + acg * 8]);
        __syncthreads();

#pragma unroll 1
        for (int kc = 0; kc < 32; kc++) {
            const int cur = kc & 1;
            float4 ra, rb;
            if (kc < 31) {
                int k0 = (kc + 1) * 32;
                ra = *reinterpret_cast<const float4*>(&ah_in[arow * 1024 + k0 + acg * 8]);
                rb = *reinterpret_cast<const float4*>(&al_in[arow * 1024 + k0 + acg * 8]);
            }
#pragma unroll
            for (int kk = 0; kk < 32; kk += 16) {
                const int r0 = mf * 16 + grp;
                const int c0 = kc * 32 + kk + 2 * t4;    // absolute k column in Wsp
                const int cs = kk + 2 * t4;              // column in staging buffer
                unsigned a_h[4], a_l[4], bh[2][2], bl[2][2];
                a_h[0] = U32(Ah[cur][r0][cs]);     a_h[1] = U32(Ah[cur][r0 + 8][cs]);
                a_h[2] = U32(Ah[cur][r0][cs + 8]); a_h[3] = U32(Ah[cur][r0 + 8][cs + 8]);
                a_l[0] = U32(Al[cur][r0][cs]);     a_l[1] = U32(Al[cur][r0 + 8][cs]);
                a_l[2] = U32(Al[cur][r0][cs + 8]); a_l[3] = U32(Al[cur][r0 + 8][cs + 8]);
#pragma unroll
                for (int q = 0; q < 2; q++) {
                    int n0 = (np * 2 + q) * 8 + grp;
                    bh[q][0] = U32(Wsp[n0][c0]);      bh[q][1] = U32(Wsp[n0][c0 + 8]);
                    bl[q][0] = U32(Wsp[32 + n0][c0]); bl[q][1] = U32(Wsp[32 + n0][c0 + 8]);
                }
                mma16816(acc[0], a_h, bh[0]); mma16816(acc[1], a_h, bh[1]);
                mma16816(acc[0], a_l, bh[0]); mma16816(acc[1], a_l, bh[1]);
                mma16816(acc[0], a_h, bl[0]); mma16816(acc[1], a_h, bl[1]);
            }
            if (kc < 31) {
                *reinterpret_cast<float4*>(&Ah[cur ^ 1][arow][acg * 8]) = ra;
                *reinterpret_cast<float4*>(&Al[cur ^ 1][arow][acg * 8]) = rb;
            }
            __syncthreads();
        }

        // z exchange
#pragma unroll
        for (int q = 0; q < 2; q++) {
            int n0 = (np * 2 + q) * 8 + 2 * t4;
            int r0 = mf * 16 + grp;
            zsm[r0][n0]         = acc[q][0];
            zsm[r0][n0 + 1]     = acc[q][1];
            zsm[r0 + 8][n0]     = acc[q][2];
            zsm[r0 + 8][n0 + 1] = acc[q][3];
        }
        __syncthreads();

        // gate math + state update
#pragma unroll
        for (int i = 0; i < 2; i++) {
            int p = tid + i * 256;
            int b = p >> 3, jl = p & 7;
            int hb = hb8 + jl;
            float zf = zsm[b][jl * 4 + 0] + xp[i].x;
            float zi = zsm[b][jl * 4 + 1] + xp[i].y;
            float zg = zsm[b][jl * 4 + 2] + xp[i].z;
            float zo = zsm[b][jl * 4 + 3] + xp[i].w;
            float f  = 1.f / (1.f + expf(-zf));
            float ig = 1.f / (1.f + expf(-zi));
            float gg = tanhf(zg);
            float oo = 1.f / (1.f + expf(-zo));
            int idx = (b << 10) + hb;
            float cn = f * c_reg[i] + ig * gg;
            c_reg[i] = cn;
            float hn = oo * tanhf(cn);
            out_t[idx] = hn;
            __half hh = __float2half_rn(hn);
            ah_out[idx] = hh;
            al_out[idx] = __float2half_rn(hn - __half2float(hh));
            if (t == T_STEPS - 1 && out_tail) {
                out_tail[idx] = hn;
                out_tail[B_SZ * H_SZ + idx] = cn;
            }
        }

        // grid barrier (skip after last step)
        if (t < T_STEPS - 1) {
            __threadfence();
            __syncthreads();
            if (tid == 0) {
                atomicAdd(&g_barc, 1u);
                unsigned target = (unsigned)(t + 1) * (unsigned)gridDim.x;
                while (ldacq(&g_barc) < target) { }
            }
            __syncthreads();
        }
    }
}

extern "C" void kernel_launch(void* const* d_in, const int* in_sizes, int n_in,
                              void* d_out, int out_size) {
    const float* inputs = (const float*)d_in[0];
    const float* Wf = (const float*)d_in[1];
    const float* bf = (const float*)d_in[2];
    const float* Wi = (const float*)d_in[3];
    const float* bi = (const float*)d_in[4];
    const float* Wg = (const float*)d_in[5];
    const float* bg = (const float*)d_in[6];
    const float* Wo = (const float*)d_in[7];
    const float* bo = (const float*)d_in[8];
    float* out = (float*)d_out;

    cudaFuncSetAttribute(gemm_xpre, cudaFuncAttributeMaxDynamicSharedMemorySize, GX_SMEM);
    cudaFuncSetAttribute(lstm_persist, cudaFuncAttributeMaxDynamicSharedMemorySize, LS_SMEM);

    pack_weights<<<(1024 * 1024 + 255) / 256, 256>>>(Wf, bf, Wi, bi, Wg, bg, Wo, bo);
    convert_x<<<(T_STEPS * B_SZ * 1024 + 255) / 256, 256>>>(inputs);
    zero_state<<<(B_SZ * H_SZ + 255) / 256, 256>>>();

    dim3 g1(NG / 128, (T_STEPS * B_SZ) / 128);
    gemm_xpre<<<g1, 256, GX_SMEM>>>();

    const int tail_needed = T_STEPS * B_SZ * H_SZ + 2 * B_SZ * H_SZ;
    float* out_tail = (out_size >= tail_needed) ? out + (size_t)T_STEPS * B_SZ * H_SZ : nullptr;
    lstm_persist<<<128, 256, LS_SMEM>>>(out, out_tail);
}

// round 6
// speedup vs baseline: 3.6091x; 1.2794x over previous
#include <cuda_runtime.h>
#include <cuda_fp16.h>
#include <math.h>

#define T_STEPS 256
#define B_SZ    64
#define H_SZ    1024
#define NG      4096   // 4*H
#define WPAD    1032   // padded k-stride for smem-resident weights (bank-safe)
#define CH      128    // k columns per staged chunk in recurrence
#define NCH     8      // chunks per step

// ---------------- device-global scratch (allocation-free contract) ---------
__device__ __half g_Wxpk[(size_t)2 * NG * 1024];            // [s][n'=j*4+g][k]
__device__ __half g_Whpk[(size_t)128 * 2 * 32 * 1024];      // [blk][s][n32][k]
__device__ float  g_bpk[NG];
__device__ __half g_axh[(size_t)T_STEPS * B_SZ * 1024];
__device__ __half g_axl[(size_t)T_STEPS * B_SZ * 1024];
__device__ float  g_Xpre[(size_t)T_STEPS * B_SZ * NG];
__device__ __half g_ah[2][B_SZ * H_SZ];                     // h (fp16), dbl-buffered
__device__ unsigned g_cnt[NCH];                             // producer-group flags

#define U32(x) (*reinterpret_cast<const unsigned*>(&(x)))

__device__ __forceinline__ void mma16816(float* c, const unsigned* a, const unsigned* b) {
    asm volatile(
        "mma.sync.aligned.m16n8k16.row.col.f32.f16.f16.f32 "
        "{%0,%1,%2,%3}, {%4,%5,%6,%7}, {%8,%9}, {%0,%1,%2,%3};\n"
        : "+f"(c[0]), "+f"(c[1]), "+f"(c[2]), "+f"(c[3])
        : "r"(a[0]), "r"(a[1]), "r"(a[2]), "r"(a[3]), "r"(b[0]), "r"(b[1]));
}

__device__ __forceinline__ void cp16(void* smem_dst, const void* gsrc) {
    unsigned s = (unsigned)__cvta_generic_to_shared(smem_dst);
    asm volatile("cp.async.cg.shared.global [%0], [%1], 16;\n" :: "r"(s), "l"(gsrc));
}

__device__ __forceinline__ unsigned ldacq(const unsigned* p) {
    unsigned v;
    asm volatile("ld.acquire.gpu.global.u32 %0, [%1];" : "=r"(v) : "l"(p) : "memory");
    return v;
}

__device__ __forceinline__ void spin_ge(const unsigned* p, unsigned tgt) {
    while (ldacq(p) < tgt) { }
}

// ---------------------------------------------------------------------------
// Pack weights (split fp16 hi/lo, n-major, gate-interleaved; per-block gather
// for the recurrence).
// ---------------------------------------------------------------------------
__global__ void pack_weights(const float* __restrict__ Wff, const float* __restrict__ bff,
                             const float* __restrict__ Wii, const float* __restrict__ bii,
                             const float* __restrict__ Wgg, const float* __restrict__ bgg,
                             const float* __restrict__ Woo, const float* __restrict__ boo) {
    int idx = blockIdx.x * blockDim.x + threadIdx.x;
    if (idx >= 1024 * 1024) return;
    int j = idx >> 10, k = idx & 1023;
    const float* Wm[4] = {Wff, Wii, Wgg, Woo};
    const float* bm[4] = {bff, bii, bgg, boo};
#pragma unroll
    for (int g = 0; g < 4; g++) {
        float vx = Wm[g][(size_t)j * 2048 + k];
        float vh = Wm[g][(size_t)j * 2048 + 1024 + k];
        __half xh = __float2half_rn(vx);
        __half xl = __float2half_rn(vx - __half2float(xh));
        __half hh = __float2half_rn(vh);
        __half hl = __float2half_rn(vh - __half2float(hh));
        int np = j * 4 + g;
        g_Wxpk[(size_t)np * 1024 + k]        = xh;
        g_Wxpk[(size_t)(NG + np) * 1024 + k] = xl;
        int b = j >> 3, jl = j & 7, n32 = jl * 4 + g;
        g_Whpk[(((size_t)b * 2 + 0) * 32 + n32) * 1024 + k] = hh;
        g_Whpk[(((size_t)b * 2 + 1) * 32 + n32) * 1024 + k] = hl;
        if (k == 0) g_bpk[np] = bm[g][j];
    }
}

__global__ void convert_x(const float* __restrict__ x) {
    int idx = blockIdx.x * blockDim.x + threadIdx.x;
    if (idx >= T_STEPS * B_SZ * 1024) return;
    float v = x[idx];
    __half h = __float2half_rn(v);
    g_axh[idx] = h;
    g_axl[idx] = __float2half_rn(v - __half2float(h));
}

__global__ void zero_state() {
    int i = blockIdx.x * blockDim.x + threadIdx.x;
    if (i < B_SZ * H_SZ) {
        g_ah[0][i] = __float2half_rn(0.f);
    }
    if (blockIdx.x == 0 && threadIdx.x < NCH) g_cnt[threadIdx.x] = 0u;
}

// ---------------------------------------------------------------------------
// Precompute: Xpre = [xh|xl] @ Wx (3-pass compensated), 128x128 tile, BK=32,
// 2-stage cp.async pipeline. (unchanged this round)
// ---------------------------------------------------------------------------
#define GX_SMEM (8 * 128 * 40 * 2)

__device__ __forceinline__ void gx_issue(char* sm, int st, int kc, int tid, int mb, int nb) {
    __half(*Axh)[128][40] = reinterpret_cast<__half(*)[128][40]>(sm);
    __half(*Axl)[128][40] = reinterpret_cast<__half(*)[128][40]>(sm + 20480);
    __half(*Whs)[128][40] = reinterpret_cast<__half(*)[128][40]>(sm + 40960);
    __half(*Wls)[128][40] = reinterpret_cast<__half(*)[128][40]>(sm + 61440);
    const int k0 = kc * 32;
#pragma unroll
    for (int i = 0; i < 2; i++) {
        int e = tid + i * 256;
        int row = e >> 2, cg = e & 3;
        cp16(&Axh[st][row][cg * 8], &g_axh[(size_t)(mb * 128 + row) * 1024 + k0 + cg * 8]);
        cp16(&Axl[st][row][cg * 8], &g_axl[(size_t)(mb * 128 + row) * 1024 + k0 + cg * 8]);
        cp16(&Whs[st][row][cg * 8], &g_Wxpk[(size_t)(nb * 128 + row) * 1024 + k0 + cg * 8]);
        cp16(&Wls[st][row][cg * 8], &g_Wxpk[(size_t)(NG + nb * 128 + row) * 1024 + k0 + cg * 8]);
    }
    asm volatile("cp.async.commit_group;\n" ::);
}

__global__ __launch_bounds__(256, 2) void gemm_xpre() {
    extern __shared__ char sm[];
    __half(*Axh)[128][40] = reinterpret_cast<__half(*)[128][40]>(sm);
    __half(*Axl)[128][40] = reinterpret_cast<__half(*)[128][40]>(sm + 20480);
    __half(*Whs)[128][40] = reinterpret_cast<__half(*)[128][40]>(sm + 40960);
    __half(*Wls)[128][40] = reinterpret_cast<__half(*)[128][40]>(sm + 61440);

    const int tid = threadIdx.x;
    const int lane = tid & 31, w = tid >> 5;
    const int grp = lane >> 2, t4 = lane & 3;
    const int wm = w >> 2, wn = w & 3;
    const int nb = blockIdx.x, mb = blockIdx.y;

    float acc[4][4][4];
#pragma unroll
    for (int m = 0; m < 4; m++)
#pragma unroll
        for (int n = 0; n < 4; n++)
#pragma unroll
            for (int i = 0; i < 4; i++) acc[m][n][i] = 0.f;

    gx_issue(sm, 0, 0, tid, mb, nb);

    for (int kc = 0; kc < 32; ++kc) {
        const int cur = kc & 1;
        if (kc + 1 < 32) gx_issue(sm, cur ^ 1, kc + 1, tid, mb, nb);
        if (kc + 1 < 32) asm volatile("cp.async.wait_group 1;\n" ::);
        else             asm volatile("cp.async.wait_group 0;\n" ::);
        __syncthreads();

#pragma unroll
        for (int kk = 0; kk < 32; kk += 16) {
            unsigned af[4][4], bf2[4][2];
            const int c = kk + 2 * t4;
#pragma unroll
            for (int m = 0; m < 4; m++) {
                int r = wm * 64 + m * 16 + grp;
                af[m][0] = U32(Axh[cur][r][c]);     af[m][1] = U32(Axh[cur][r + 8][c]);
                af[m][2] = U32(Axh[cur][r][c + 8]); af[m][3] = U32(Axh[cur][r + 8][c + 8]);
            }
#pragma unroll
            for (int n = 0; n < 4; n++) {
                int rn = wn * 32 + n * 8 + grp;
                bf2[n][0] = U32(Whs[cur][rn][c]); bf2[n][1] = U32(Whs[cur][rn][c + 8]);
            }
#pragma unroll
            for (int m = 0; m < 4; m++)
#pragma unroll
                for (int n = 0; n < 4; n++) mma16816(acc[m][n], af[m], bf2[n]);
#pragma unroll
            for (int n = 0; n < 4; n++) {
                int rn = wn * 32 + n * 8 + grp;
                bf2[n][0] = U32(Wls[cur][rn][c]); bf2[n][1] = U32(Wls[cur][rn][c + 8]);
            }
#pragma unroll
            for (int m = 0; m < 4; m++)
#pragma unroll
                for (int n = 0; n < 4; n++) mma16816(acc[m][n], af[m], bf2[n]);
#pragma unroll
            for (int m = 0; m < 4; m++) {
                int r = wm * 64 + m * 16 + grp;
                af[m][0] = U32(Axl[cur][r][c]);     af[m][1] = U32(Axl[cur][r + 8][c]);
                af[m][2] = U32(Axl[cur][r][c + 8]); af[m][3] = U32(Axl[cur][r + 8][c + 8]);
            }
#pragma unroll
            for (int n = 0; n < 4; n++) {
                int rn = wn * 32 + n * 8 + grp;
                bf2[n][0] = U32(Whs[cur][rn][c]); bf2[n][1] = U32(Whs[cur][rn][c + 8]);
            }
#pragma unroll
            for (int m = 0; m < 4; m++)
#pragma unroll
                for (int n = 0; n < 4; n++) mma16816(acc[m][n], af[m], bf2[n]);
        }
        __syncthreads();
    }

#pragma unroll
    for (int m = 0; m < 4; m++) {
        int r = mb * 128 + wm * 64 + m * 16 + grp;
#pragma unroll
        for (int n = 0; n < 4; n++) {
            int cn = nb * 128 + wn * 32 + n * 8 + 2 * t4;
            float b0 = __ldg(&g_bpk[cn]), b1 = __ldg(&g_bpk[cn + 1]);
            float2 v0 = make_float2(acc[m][n][0] + b0, acc[m][n][1] + b1);
            float2 v1 = make_float2(acc[m][n][2] + b0, acc[m][n][3] + b1);
            *reinterpret_cast<float2*>(&g_Xpre[(size_t)r * NG + cn]) = v0;
            *reinterpret_cast<float2*>(&g_Xpre[(size_t)(r + 8) * NG + cn]) = v1;
        }
    }
}

// ---------------------------------------------------------------------------
// Persistent recurrence, fine-grained sync. 128 blocks x 256 threads.
// 2 MMA passes: h_q*W_h + h_q*W_l (weight split kept; h residual dropped).
// Per-chunk producer-group flags replace the full grid barrier.
// ---------------------------------------------------------------------------
#define LS_W_OFF   0
#define LS_AH_OFF  132096                       // 64 x WPAD halves
#define LS_Z_OFF   (LS_AH_OFF + 2 * 64 * 136 * 2)
#define LS_SMEM    (LS_Z_OFF + 64 * 36 * 4)     // 210944 B

__global__ __launch_bounds__(256, 1) void lstm_persist(float* __restrict__ out,
                                                       float* __restrict__ out_tail) {
    extern __shared__ char sm[];
    __half(*Wsp)[WPAD]      = reinterpret_cast<__half(*)[WPAD]>(sm + LS_W_OFF);
    __half(*Ah)[64][136]    = reinterpret_cast<__half(*)[64][136]>(sm + LS_AH_OFF);
    float(*zsm)[36]         = reinterpret_cast<float(*)[36]>(sm + LS_Z_OFF);

    const int tid = threadIdx.x;
    const int lane = tid & 31, w = tid >> 5;
    const int grp = lane >> 2, t4 = lane & 3;
    const int mf = w & 3, np = w >> 2;
    const int hb8 = blockIdx.x * 8;
    const int arow = tid >> 2, acseg = (tid & 3) * 32;   // staging map
    const unsigned mygrp = (unsigned)(blockIdx.x >> 4);

    // ---- load this block's Wh slice (hi 32 rows + lo 32 rows) once ----
    const size_t wsrc = (size_t)blockIdx.x * 65536;
    for (int i = tid; i < 8192; i += 256) {
        int sn = i >> 7, kc8 = i & 127;
        *reinterpret_cast<float4*>(&Wsp[sn][kc8 * 8]) =
            *reinterpret_cast<const float4*>(&g_Whpk[wsrc + (size_t)sn * 1024 + kc8 * 8]);
    }
    __syncthreads();

    float c_reg[2] = {0.f, 0.f};

#pragma unroll 1
    for (int t = 0; t < T_STEPS; t++) {
        const __half* __restrict__ ah_in = g_ah[t & 1];
        __half* __restrict__ ah_out = g_ah[(t + 1) & 1];
        const float* __restrict__ xpre_t = g_Xpre + (size_t)t * (B_SZ * NG);
        float* __restrict__ out_t = out + (size_t)t * (B_SZ * H_SZ);
        const unsigned tgt = 16u * (unsigned)t;

        // prefetch this step's xpre gate-vectors
        float4 xp[2];
#pragma unroll
        for (int i = 0; i < 2; i++) {
            int p = tid + i * 256;
            int b = p >> 3, jl = p & 7;
            xp[i] = *reinterpret_cast<const float4*>(&xpre_t[(size_t)b * NG + (hb8 + jl) * 4]);
        }

        float acc[2][4] = {{0.f, 0.f, 0.f, 0.f}, {0.f, 0.f, 0.f, 0.f}};

        // chunk 0: wait + load into buf 0
        if (t) spin_ge(&g_cnt[0], tgt);
        {
            const __half* src = &ah_in[arow * 1024 + acseg];
            float4 s0 = *reinterpret_cast<const float4*>(src);
            float4 s1 = *reinterpret_cast<const float4*>(src + 8);
            float4 s2 = *reinterpret_cast<const float4*>(src + 16);
            float4 s3 = *reinterpret_cast<const float4*>(src + 24);
            __half* dst = &Ah[0][arow][acseg];
            *reinterpret_cast<float4*>(dst)      = s0;
            *reinterpret_cast<float4*>(dst + 8)  = s1;
            *reinterpret_cast<float4*>(dst + 16) = s2;
            *reinterpret_cast<float4*>(dst + 24) = s3;
        }
        __syncthreads();

#pragma unroll 1
        for (int c = 0; c < NCH; c++) {
            const int cur = c & 1;
            float4 r0v, r1v, r2v, r3v;
            if (c < NCH - 1) {
                if (t) spin_ge(&g_cnt[c + 1], tgt);
                const __half* src = &ah_in[arow * 1024 + (c + 1) * CH + acseg];
                r0v = *reinterpret_cast<const float4*>(src);
                r1v = *reinterpret_cast<const float4*>(src + 8);
                r2v = *reinterpret_cast<const float4*>(src + 16);
                r3v = *reinterpret_cast<const float4*>(src + 24);
            }
#pragma unroll
            for (int kk = 0; kk < CH; kk += 16) {
                const int r0 = mf * 16 + grp;
                const int cs = kk + 2 * t4;
                const int c0 = c * CH + cs;
                unsigned a[4], bh[2][2], bl[2][2];
                a[0] = U32(Ah[cur][r0][cs]);     a[1] = U32(Ah[cur][r0 + 8][cs]);
                a[2] = U32(Ah[cur][r0][cs + 8]); a[3] = U32(Ah[cur][r0 + 8][cs + 8]);
#pragma unroll
                for (int q = 0; q < 2; q++) {
                    int n0 = (np * 2 + q) * 8 + grp;
                    bh[q][0] = U32(Wsp[n0][c0]);      bh[q][1] = U32(Wsp[n0][c0 + 8]);
                    bl[q][0] = U32(Wsp[32 + n0][c0]); bl[q][1] = U32(Wsp[32 + n0][c0 + 8]);
                }
                mma16816(acc[0], a, bh[0]); mma16816(acc[1], a, bh[1]);
                mma16816(acc[0], a, bl[0]); mma16816(acc[1], a, bl[1]);
            }
            if (c < NCH - 1) {
                __half* dst = &Ah[cur ^ 1][arow][acseg];
                *reinterpret_cast<float4*>(dst)      = r0v;
                *reinterpret_cast<float4*>(dst + 8)  = r1v;
                *reinterpret_cast<float4*>(dst + 16) = r2v;
                *reinterpret_cast<float4*>(dst + 24) = r3v;
            }
            __syncthreads();
        }

        // z exchange
#pragma unroll
        for (int q = 0; q < 2; q++) {
            int n0 = (np * 2 + q) * 8 + 2 * t4;
            int r0 = mf * 16 + grp;
            zsm[r0][n0]         = acc[q][0];
            zsm[r0][n0 + 1]     = acc[q][1];
            zsm[r0 + 8][n0]     = acc[q][2];
            zsm[r0 + 8][n0 + 1] = acc[q][3];
        }
        __syncthreads();

        // gate math + state update; publish h first, then arrive, then out
        float hn_r[2], cn_r[2];
        int idx_r[2];
#pragma unroll
        for (int i = 0; i < 2; i++) {
            int p = tid + i * 256;
            int b = p >> 3, jl = p & 7;
            int hb = hb8 + jl;
            float zf = zsm[b][jl * 4 + 0] + xp[i].x;
            float zi = zsm[b][jl * 4 + 1] + xp[i].y;
            float zg = zsm[b][jl * 4 + 2] + xp[i].z;
            float zo = zsm[b][jl * 4 + 3] + xp[i].w;
            float f  = 1.f / (1.f + expf(-zf));
            float ig = 1.f / (1.f + expf(-zi));
            float gg = tanhf(zg);
            float oo = 1.f / (1.f + expf(-zo));
            int idx = (b << 10) + hb;
            float cn = f * c_reg[i] + ig * gg;
            c_reg[i] = cn;
            float hn = oo * tanhf(cn);
            ah_out[idx] = __float2half_rn(hn);
            hn_r[i] = hn; cn_r[i] = cn; idx_r[i] = idx;
        }
        __threadfence();
        __syncthreads();
        if (tid == 0) atomicAdd(&g_cnt[mygrp], 1u);

#pragma unroll
        for (int i = 0; i < 2; i++) out_t[idx_r[i]] = hn_r[i];
        if (t == T_STEPS - 1 && out_tail) {
#pragma unroll
            for (int i = 0; i < 2; i++) {
                out_tail[idx_r[i]] = hn_r[i];
                out_tail[B_SZ * H_SZ + idx_r[i]] = cn_r[i];
            }
        }
    }
}

extern "C" void kernel_launch(void* const* d_in, const int* in_sizes, int n_in,
                              void* d_out, int out_size) {
    const float* inputs = (const float*)d_in[0];
    const float* Wf = (const float*)d_in[1];
    const float* bf = (const float*)d_in[2];
    const float* Wi = (const float*)d_in[3];
    const float* bi = (const float*)d_in[4];
    const float* Wg = (const float*)d_in[5];
    const float* bg = (const float*)d_in[6];
    const float* Wo = (const float*)d_in[7];
    const float* bo = (const float*)d_in[8];
    float* out = (float*)d_out;

    cudaFuncSetAttribute(gemm_xpre, cudaFuncAttributeMaxDynamicSharedMemorySize, GX_SMEM);
    cudaFuncSetAttribute(lstm_persist, cudaFuncAttributeMaxDynamicSharedMemorySize, LS_SMEM);

    pack_weights<<<(1024 * 1024 + 255) / 256, 256>>>(Wf, bf, Wi, bi, Wg, bg, Wo, bo);
    convert_x<<<(T_STEPS * B_SZ * 1024 + 255) / 256, 256>>>(inputs);
    zero_state<<<(B_SZ * H_SZ + 255) / 256, 256>>>();

    dim3 g1(NG / 128, (T_STEPS * B_SZ) / 128);
    gemm_xpre<<<g1, 256, GX_SMEM>>>();

    const int tail_needed = T_STEPS * B_SZ * H_SZ + 2 * B_SZ * H_SZ;
    float* out_tail = (out_size >= tail_needed) ? out + (size_t)T_STEPS * B_SZ * H_SZ : nullptr;
    lstm_persist<<<128, 256, LS_SMEM>>>(out, out_tail);
}